// round 12
// baseline (speedup 1.0000x reference)
#include <cuda_runtime.h>
#include <math.h>
#include <stdint.h>

#define S 1024
#define SS (S*S)
#define NBH 4096
#define CAP 512
#define TARGETN 384u
#define MAXR 256
#define NKP 17
#define HOTCAP 8192
#define NW2 12              // 384/32 bitset words for MIS
#define MPAD 13             // padded row stride (13 coprime 32 -> conflict-free)
#define FULL 0xFFFFFFFFu

#define HOTB  0x3F733333u   // __float_as_uint(0.95f)
#define HRNG  (0x3F800000u - 0x3F733333u)

// ---------------- scratch (static __device__, zero at module load) ----------
__device__ unsigned int       g_hist[NBH];
__device__ unsigned int       g_cnt_hot;
__device__ unsigned long long g_hot[HOTCAP];   // hot candidates (bits<<32 | ~idx)
__device__ int                g_selx[MAXR], g_sely[MAXR];
__device__ int                g_nsel;

static __device__ __forceinline__ unsigned bucket_hot(unsigned bits) {
    unsigned d = bits - HOTB;
    unsigned b = (unsigned)(((unsigned long long)d * NBH) / HRNG);
    return b >= NBH ? (NBH - 1) : b;
}

// ---------------- K1: scan heatmap; keep only conf>=0.95 candidates ---------
__global__ void __launch_bounds__(512) k_scan(const float* __restrict__ x) {
    const float4* __restrict__ x4 = (const float4*)x;
    int i = blockIdx.x * blockDim.x + threadIdx.x;   // SS/8 threads
    int lane = threadIdx.x & 31;

    float4 a0 = x4[i];
    float4 a1 = x4[i + SS / 8];
    float vs[8] = {a0.x, a0.y, a0.z, a0.w, a1.x, a1.y, a1.z, a1.w};

    unsigned long long keys[8];
    unsigned bbits[8];
    int cnt = 0;
    #pragma unroll
    for (int c = 0; c < 8; c++) {
        float v = vs[c];
        if (v > 2.9f) {  // prefilter; exact test on conf bits below
            float conf = 1.0f / (1.0f + expf(-v));   // same formula as reference
            unsigned bits = __float_as_uint(conf);
            if (bits >= HOTB) {
                int idx = (c < 4) ? (4 * i + c) : (4 * (i + SS / 8) + (c - 4));
                keys[cnt]  = ((unsigned long long)bits << 32) | (unsigned)(~idx);
                bbits[cnt] = bits;
                cnt++;
            }
        }
    }
    if (__ballot_sync(FULL, cnt) == 0u) return;   // ~99% of warps exit here

    unsigned pre = (unsigned)cnt;
    #pragma unroll
    for (int off = 1; off < 32; off <<= 1) {
        unsigned v = __shfl_up_sync(FULL, pre, off);
        if (lane >= off) pre += v;
    }
    unsigned total = __shfl_sync(FULL, pre, 31);
    unsigned base = 0;
    if (lane == 31) base = atomicAdd(&g_cnt_hot, total);
    base = __shfl_sync(FULL, base, 31);
    unsigned mybase = base + pre - (unsigned)cnt;
    for (int c = 0; c < cnt; c++) {
        unsigned p = mybase + c;
        if (p < HOTCAP) g_hot[p] = keys[c];
        atomicAdd(&g_hist[bucket_hot(bbits[c])], 1u);   // RED
    }
}

// ---------------- K2: cutoff + collect + reg-sort + build + word-serial MIS -
__global__ void __launch_bounds__(1024, 1) k_mid() {
    __shared__ unsigned long long sk[CAP];          // 4 KB (buffer A)
    __shared__ unsigned long long sk2[CAP];         // 4 KB (buffer B)
    __shared__ float2  pos[CAP];                    // 4 KB
    __shared__ unsigned s_mtx[384 * MPAD];          // ~19.5 KB conflict matrix
    __shared__ unsigned cs[1024];
    __shared__ unsigned seg_suf[32];
    __shared__ unsigned s_cut;
    __shared__ unsigned s_cnt;
    __shared__ unsigned sm32[32];
    __shared__ unsigned s_accw[NW2];

    int t = threadIdx.x;
    int lane = t & 31;

    // --- phase A: per-4-bucket partial sums + init ---
    {
        unsigned s = 0;
        #pragma unroll
        for (int b = 0; b < 4; b++) s += g_hist[t * 4 + b];
        cs[t] = s;
        if (t == 0) s_cnt = 0u;
        if (t < CAP) sk[t] = 0ULL;
    }
    __syncthreads();

    // --- phase B: parallel cutoff; strictly above boundary bucket ---
    if (t < 32) {
        unsigned a = 0;
        #pragma unroll
        for (int b = 0; b < 32; b++) a += cs[lane * 32 + b];
        unsigned suf = a;
        #pragma unroll
        for (int off = 1; off < 32; off <<= 1) {
            unsigned v = __shfl_down_sync(FULL, suf, off);
            if (lane + off < 32) suf += v;
        }
        seg_suf[lane] = suf;
        __syncwarp(FULL);
        unsigned bal = __ballot_sync(FULL, suf >= TARGETN);
        if (lane == 0) {
            if (bal == 0u) { s_cut = 0u; }  // total hot < TARGETN: keep all (<384)
            else {
                int lseg = 31 - __clz(bal);
                unsigned base = (lseg < 31) ? seg_suf[lseg + 1] : 0u;
                unsigned cum = base;
                int ccut = lseg * 32;
                for (int c = lseg * 32 + 31; c >= lseg * 32; c--) {
                    cum += cs[c];
                    if (cum >= TARGETN) { ccut = c; break; }
                }
                unsigned cc = cum - cs[ccut];
                unsigned h[4];
                #pragma unroll
                for (int b = 0; b < 4; b++) h[b] = g_hist[ccut * 4 + b];
                int bcut = ccut * 4;
                #pragma unroll
                for (int b = 3; b >= 0; b--) {
                    cc += h[b];
                    if (cc >= TARGETN) { bcut = ccut * 4 + b; break; }
                }
                s_cut = (unsigned)bcut + 1u;  // strict-above => count < TARGETN
            }
        }
    }
    __syncthreads();

    // --- phase C: collect above cutoff (warp-aggregated smem append) --------
    {
        unsigned n = min(g_cnt_hot, (unsigned)HOTCAP);
        unsigned cut = s_cut;
        unsigned rounds = (n + 1023u) / 1024u;
        for (unsigned r = 0; r < rounds; r++) {
            unsigned i = r * 1024u + (unsigned)t;
            bool keep = false;
            unsigned long long key = 0ULL;
            if (i < n) {
                key = g_hot[i];
                keep = bucket_hot((unsigned)(key >> 32)) >= cut;
            }
            unsigned bal = __ballot_sync(FULL, keep);
            if (bal) {
                unsigned wcnt = __popc(bal);
                unsigned base = 0;
                if (lane == 0) base = atomicAdd(&s_cnt, wcnt);
                base = __shfl_sync(FULL, base, 0);
                if (keep) {
                    unsigned p = base + __popc(bal & ((1u << lane) - 1u));
                    if (p < CAP) sk[p] = key;
                }
            }
        }
    }
    __syncthreads();

    // --- phase D: register bitonic sort desc, ping-pong smem (1 bar/stage) --
    unsigned long long key = (t < CAP) ? sk[t] : 0ULL;
    {
        int pp = 0;
        for (int k = 2; k <= CAP; k <<= 1) {
            for (int j = k >> 1; j > 0; j >>= 1) {
                unsigned long long other;
                if (j >= 32) {
                    unsigned long long* wbuf = pp ? sk2 : sk;
                    if (t < CAP) wbuf[t] = key;
                    __syncthreads();
                    other = (t < CAP) ? wbuf[t ^ j] : key;
                    pp ^= 1;
                } else {
                    other = __shfl_xor_sync(FULL, key, j);
                }
                bool keepMax = (((t & j) == 0) == ((t & k) == 0));
                if (keepMax ? (other > key) : (other < key)) key = other;
            }
        }
    }
    unsigned m = min(s_cnt, (unsigned)CAP);   // m < 384 guaranteed
    if (t < CAP) {
        unsigned idx = ~(unsigned)key;
        pos[t] = make_float2((float)(idx & (S - 1)), (float)(idx >> 10));
    }
    __syncthreads();

    // --- phase E1: build triangular conflict matrix (2 thr/candidate, all-write)
    {
        int i   = (t < 384) ? t : t - 384;
        int par = (t < 384) ? 0 : 1;
        if (t < 768 && i < (int)m) {
            float2 p = pos[i];
            int wi2 = i >> 5;
            int li = i & 31;
            for (int w = par; w <= wi2; w += 2) {
                int jmax = (w == wi2) ? li : 32;
                unsigned mw = 0u;
                for (int l = 0; l < jmax; l++) {
                    float2 q = pos[w * 32 + l];   // broadcast LDS
                    float dx = p.x - q.x, dy = p.y - q.y;
                    if (dx * dx + dy * dy <= 100.0f) mw |= 1u << l;
                }
                s_mtx[i * MPAD + w] = mw;        // unconditional: no pre-zeroing
            }
        }
    }
    __syncthreads();

    // --- phase E2: word-serial MIS on warp 0, uniform intra-word resolve ----
    if (t < 32) {
        unsigned accw[NW2];
        #pragma unroll
        for (int w = 0; w < NW2; w++) accw[w] = 0u;
        int nwords = ((int)m + 31) >> 5;
        for (int w = 0; w < nwords; w++) {
            int i = w * 32 + lane;
            bool valid = (i < (int)m);
            unsigned rej = 0u;
            for (int v = 0; v < w; v++)
                rej |= (valid ? s_mtx[i * MPAD + v] : 0u) & accw[v];
            unsigned mlow = valid ? s_mtx[i * MPAD + w] : 0u;
            unsigned cand = __ballot_sync(FULL, valid && rej == 0u);
            sm32[lane] = mlow;
            __syncwarp(FULL);
            // uniform serial resolve: every lane computes identical acc
            unsigned acc = 0u;
            #pragma unroll
            for (int l = 0; l < 32; l++) {
                unsigned ml = sm32[l];            // broadcast LDS
                if (((cand >> l) & 1u) && (ml & acc) == 0u) acc |= 1u << l;
            }
            accw[w] = acc;
            __syncwarp(FULL);
        }
        if (lane < NW2) s_accw[lane] = accw[lane];
    }
    __syncthreads();

    // --- extract accepted in rank order, cap MAXR ---
    int wi = t >> 5;
    if (t < (int)m) {
        unsigned aw = s_accw[wi];
        if ((aw >> lane) & 1u) {
            int below = 0;
            #pragma unroll
            for (int w = 0; w < NW2; w++) if (w < wi) below += __popc(s_accw[w]);
            below += __popc(aw & ((1u << lane) - 1u));
            if (below < MAXR) {
                float2 p = pos[t];
                g_selx[below] = (int)p.x;
                g_sely[below] = (int)p.y;
            }
        }
    }
    if (t == 0) {
        int tot = 0;
        #pragma unroll
        for (int w = 0; w < NW2; w++) tot += __popc(s_accw[w]);
        g_nsel = min(tot, MAXR);
    }
}

// ---------------- K3: parallel emit (one block per kp channel) --------------
// out layout (9472 f32): root[256][2] | kp[256][17][2] | valid[256]
__global__ void __launch_bounds__(256) k_emit(const float* __restrict__ x,
                                              float* __restrict__ out) {
    int b = blockIdx.x;
    int t = threadIdx.x;           // 256 threads = one root each
    int ns = g_nsel;
    const float Z = 1.41421356237309515f * 1024.0f;  // sqrt(2)*S

    if (b < NKP) {
        int r = t;
        float kx = 0.0f, ky = 0.0f;
        if (r < ns) {
            int xi = g_selx[r], yi = g_sely[r];
            int off = yi * S + xi;
            float dxv = x[(1 + 2 * b) * SS + off];
            float dyv = x[(2 + 2 * b) * SS + off];
            float ddx = tanhf(dxv) * Z, ddy = tanhf(dyv) * Z;
            kx = ddx + (float)xi;
            ky = ddy + (float)yi;
            float d = sqrtf(ddx * ddx + ddy * ddy);
            if (d < 2.0f) { kx = 0.0f; ky = 0.0f; }
            kx *= 4.0f; ky *= 4.0f;
        }
        int j = r * NKP + b;
        out[2 * MAXR + 2 * j]     = kx;
        out[2 * MAXR + 2 * j + 1] = ky;
    } else {
        // roots + valid + scratch cleanup for next replay
        int r = t;
        bool v = (r < ns);
        float fx = v ? (float)g_selx[r] : 0.0f;
        float fy = v ? (float)g_sely[r] : 0.0f;
        out[2 * r]     = fx * 4.0f;
        out[2 * r + 1] = fy * 4.0f;
        out[2 * MAXR + MAXR * 2 * NKP + r] = v ? 1.0f : 0.0f;
        for (int h = t; h < NBH; h += 256) g_hist[h] = 0u;
        if (t == 0) g_cnt_hot = 0u;
    }
}

// ---------------- entry ----------------
extern "C" void kernel_launch(void* const* d_in, const int* in_sizes, int n_in,
                              void* d_out, int out_size) {
    const float* x = (const float*)d_in[0];
    float* out = (float*)d_out;
    (void)in_sizes; (void)n_in; (void)out_size;

    k_scan<<<SS / 8 / 512, 512>>>(x);
    k_mid<<<1, 1024>>>();
    k_emit<<<NKP + 1, 256>>>(x, out);
}

// round 13
// speedup vs baseline: 1.1646x; 1.1646x over previous
#include <cuda_runtime.h>
#include <math.h>
#include <stdint.h>

#define S 1024
#define SS (S*S)
#define NBH 4096
#define CAP 512
#define TARGETN 384u
#define MAXR 256
#define NKP 17
#define HOTCAP 8192
#define NW2 12              // 384/32 bitset words for MIS
#define MPAD 13             // padded row stride (bank-conflict-free)
#define FULL 0xFFFFFFFFu

#define HOTB  0x3F733333u   // __float_as_uint(0.95f)
#define HRNG  (0x3F800000u - 0x3F733333u)

// ---------------- scratch (static __device__, zero at module load) ----------
__device__ unsigned int       g_hist[NBH];
__device__ unsigned int       g_cnt_hot;
__device__ unsigned long long g_hot[HOTCAP];   // hot candidates (bits<<32 | ~idx)
__device__ int                g_selx[MAXR], g_sely[MAXR];
__device__ int                g_nsel;

static __device__ __forceinline__ unsigned bucket_hot(unsigned bits) {
    unsigned d = bits - HOTB;
    unsigned b = (unsigned)(((unsigned long long)d * NBH) / HRNG);
    return b >= NBH ? (NBH - 1) : b;
}

// ---------------- K1: scan heatmap; keep only conf>=0.95 candidates ---------
__global__ void __launch_bounds__(512) k_scan(const float* __restrict__ x) {
    const float4* __restrict__ x4 = (const float4*)x;
    int i = blockIdx.x * blockDim.x + threadIdx.x;   // SS/8 threads
    int lane = threadIdx.x & 31;

    float4 a0 = x4[i];
    float4 a1 = x4[i + SS / 8];
    float vs[8] = {a0.x, a0.y, a0.z, a0.w, a1.x, a1.y, a1.z, a1.w};

    unsigned long long keys[8];
    unsigned bbits[8];
    int cnt = 0;
    #pragma unroll
    for (int c = 0; c < 8; c++) {
        float v = vs[c];
        if (v > 2.9f) {  // prefilter; exact test on conf bits below
            float conf = 1.0f / (1.0f + expf(-v));   // same formula as reference
            unsigned bits = __float_as_uint(conf);
            if (bits >= HOTB) {
                int idx = (c < 4) ? (4 * i + c) : (4 * (i + SS / 8) + (c - 4));
                keys[cnt]  = ((unsigned long long)bits << 32) | (unsigned)(~idx);
                bbits[cnt] = bits;
                cnt++;
            }
        }
    }
    if (__ballot_sync(FULL, cnt) == 0u) return;   // ~99% of warps exit here

    unsigned pre = (unsigned)cnt;
    #pragma unroll
    for (int off = 1; off < 32; off <<= 1) {
        unsigned v = __shfl_up_sync(FULL, pre, off);
        if (lane >= off) pre += v;
    }
    unsigned total = __shfl_sync(FULL, pre, 31);
    unsigned base = 0;
    if (lane == 31) base = atomicAdd(&g_cnt_hot, total);
    base = __shfl_sync(FULL, base, 31);
    unsigned mybase = base + pre - (unsigned)cnt;
    for (int c = 0; c < cnt; c++) {
        unsigned p = mybase + c;
        if (p < HOTCAP) g_hot[p] = keys[c];
        atomicAdd(&g_hist[bucket_hot(bbits[c])], 1u);   // RED
    }
}

// ---------------- K2: cutoff + collect + reg-sort + build + pingpong-MIS ----
__global__ void __launch_bounds__(1024, 1) k_mid() {
    __shared__ unsigned long long sk[CAP];          // 4 KB (buffer A)
    __shared__ unsigned long long sk2[CAP];         // 4 KB (buffer B)
    __shared__ float2  pos[CAP];                    // 4 KB
    __shared__ unsigned s_mtx[384 * MPAD];          // ~19.5 KB conflict matrix
    __shared__ unsigned cs[1024];
    __shared__ unsigned seg_suf[32];
    __shared__ unsigned s_cut;
    __shared__ unsigned s_cnt;
    __shared__ unsigned s_und[2][NW2], s_acc[2][NW2];
    __shared__ unsigned s_accw[NW2];

    int t = threadIdx.x;
    int lane = t & 31;

    // --- phase A: per-4-bucket partial sums + init ---
    {
        unsigned s = 0;
        #pragma unroll
        for (int b = 0; b < 4; b++) s += g_hist[t * 4 + b];
        cs[t] = s;
        if (t == 0) s_cnt = 0u;
        if (t < CAP) sk[t] = 0ULL;
    }
    __syncthreads();

    // --- phase B: parallel cutoff; strictly above boundary bucket ---
    if (t < 32) {
        unsigned a = 0;
        #pragma unroll
        for (int b = 0; b < 32; b++) a += cs[lane * 32 + b];
        unsigned suf = a;
        #pragma unroll
        for (int off = 1; off < 32; off <<= 1) {
            unsigned v = __shfl_down_sync(FULL, suf, off);
            if (lane + off < 32) suf += v;
        }
        seg_suf[lane] = suf;
        __syncwarp(FULL);
        unsigned bal = __ballot_sync(FULL, suf >= TARGETN);
        if (lane == 0) {
            if (bal == 0u) { s_cut = 0u; }  // total hot < TARGETN: keep all (<384)
            else {
                int lseg = 31 - __clz(bal);
                unsigned base = (lseg < 31) ? seg_suf[lseg + 1] : 0u;
                unsigned cum = base;
                int ccut = lseg * 32;
                for (int c = lseg * 32 + 31; c >= lseg * 32; c--) {
                    cum += cs[c];
                    if (cum >= TARGETN) { ccut = c; break; }
                }
                unsigned cc = cum - cs[ccut];
                unsigned h[4];
                #pragma unroll
                for (int b = 0; b < 4; b++) h[b] = g_hist[ccut * 4 + b];
                int bcut = ccut * 4;
                #pragma unroll
                for (int b = 3; b >= 0; b--) {
                    cc += h[b];
                    if (cc >= TARGETN) { bcut = ccut * 4 + b; break; }
                }
                s_cut = (unsigned)bcut + 1u;  // strict-above => count < TARGETN
            }
        }
    }
    __syncthreads();

    // --- phase C: collect above cutoff (warp-aggregated smem append) --------
    {
        unsigned n = min(g_cnt_hot, (unsigned)HOTCAP);
        unsigned cut = s_cut;
        unsigned rounds = (n + 1023u) / 1024u;
        for (unsigned r = 0; r < rounds; r++) {
            unsigned i = r * 1024u + (unsigned)t;
            bool keep = false;
            unsigned long long key = 0ULL;
            if (i < n) {
                key = g_hot[i];
                keep = bucket_hot((unsigned)(key >> 32)) >= cut;
            }
            unsigned bal = __ballot_sync(FULL, keep);
            if (bal) {
                unsigned wcnt = __popc(bal);
                unsigned base = 0;
                if (lane == 0) base = atomicAdd(&s_cnt, wcnt);
                base = __shfl_sync(FULL, base, 0);
                if (keep) {
                    unsigned p = base + __popc(bal & ((1u << lane) - 1u));
                    if (p < CAP) sk[p] = key;
                }
            }
        }
    }
    __syncthreads();

    // --- phase D: register bitonic sort desc, ping-pong smem (1 bar/stage) --
    unsigned long long key = (t < CAP) ? sk[t] : 0ULL;
    {
        int pp = 0;
        for (int k = 2; k <= CAP; k <<= 1) {
            for (int j = k >> 1; j > 0; j >>= 1) {
                unsigned long long other;
                if (j >= 32) {
                    unsigned long long* wbuf = pp ? sk2 : sk;
                    if (t < CAP) wbuf[t] = key;
                    __syncthreads();
                    other = (t < CAP) ? wbuf[t ^ j] : key;
                    pp ^= 1;
                } else {
                    other = __shfl_xor_sync(FULL, key, j);
                }
                bool keepMax = (((t & j) == 0) == ((t & k) == 0));
                if (keepMax ? (other > key) : (other < key)) key = other;
            }
        }
    }
    unsigned m = min(s_cnt, (unsigned)CAP);   // m < 384 guaranteed
    if (t < CAP) {
        unsigned idx = ~(unsigned)key;
        pos[t] = make_float2((float)(idx & (S - 1)), (float)(idx >> 10));
    }
    // zero conflict matrix + init MIS state (buffer 0)
    for (int i = t; i < 384 * MPAD; i += 1024) s_mtx[i] = 0u;
    {
        unsigned alive = __ballot_sync(FULL, t < (int)m);
        if (t < NW2 * 32 && lane == 0) { s_und[0][t >> 5] = alive; s_acc[0][t >> 5] = 0u; }
    }
    __syncthreads();

    // --- phase E1: split-build triangular conflict matrix (2 thr/candidate) -
    {
        int i   = (t < 384) ? t : t - 384;
        int par = (t < 384) ? 0 : 1;
        if (t < 768 && i < (int)m) {
            float2 p = pos[i];
            int wi2 = i >> 5;
            int li = i & 31;
            for (int w = par; w <= wi2; w += 2) {
                int jmax = (w == wi2) ? li : 32;
                unsigned mw = 0u;
                for (int l = 0; l < jmax; l++) {
                    float2 q = pos[w * 32 + l];   // broadcast LDS
                    float dx = p.x - q.x, dy = p.y - q.y;
                    if (dx * dx + dy * dy <= 100.0f) mw |= 1u << l;
                }
                if (mw) s_mtx[i * MPAD + w] = mw;
            }
        }
    }
    __syncthreads();

    // --- phase E2: lexicographic MIS relaxation, warps 0-11 only ------------
    // (named barrier over 384 threads; warps 12-31 wait at the closing sync)
    if (t < 384) {
        float2 myp = (t < (int)m) ? pos[t] : make_float2(0.f, 0.f);
        int wi = t >> 5;
        unsigned msk[NW2];
        #pragma unroll
        for (int w = 0; w < NW2; w++) msk[w] = 0u;
        if (t < (int)m) {
            #pragma unroll
            for (int w = 0; w < NW2; w++) msk[w] = s_mtx[t * MPAD + w];
        }
        bool undec = (t < (int)m);
        bool isacc = false;
        int cur = 0;

        for (int round = 0; round < 384; round++) {
            unsigned u[NW2], a[NW2], u_all = 0u;
            #pragma unroll
            for (int w = 0; w < NW2; w++) {
                u[w] = s_und[cur][w];
                a[w] = s_acc[cur][w];
                u_all |= u[w];
            }
            if (u_all == 0u) break;          // uniform (same smem for all)
            if (undec) {
                unsigned pend = 0u, accc = 0u;
                #pragma unroll
                for (int w = 0; w < NW2; w++) { pend |= msk[w] & u[w]; accc |= msk[w] & a[w]; }
                if (pend == 0u) { undec = false; isacc = (accc == 0u); }
            }
            unsigned uw = __ballot_sync(FULL, undec);
            unsigned aw = __ballot_sync(FULL, isacc);
            if (lane == 0) {
                s_und[cur ^ 1][wi] = uw;
                s_acc[cur ^ 1][wi] = aw;
            }
            asm volatile("bar.sync 1, 384;" ::: "memory");
            cur ^= 1;
        }
        // republish final accepted words at stable location
        if (t < NW2) s_accw[t] = s_acc[cur][t];
    }
    __syncthreads();

    // --- extract accepted in rank order, cap MAXR ---
    if (t < (int)m) {
        int wi = t >> 5;
        unsigned aw = s_accw[wi];
        if ((aw >> lane) & 1u) {
            int below = 0;
            #pragma unroll
            for (int w = 0; w < NW2; w++) if (w < wi) below += __popc(s_accw[w]);
            below += __popc(aw & ((1u << lane) - 1u));
            if (below < MAXR) {
                float2 p = pos[t];
                g_selx[below] = (int)p.x;
                g_sely[below] = (int)p.y;
            }
        }
    }
    if (t == 0) {
        int tot = 0;
        #pragma unroll
        for (int w = 0; w < NW2; w++) tot += __popc(s_accw[w]);
        g_nsel = min(tot, MAXR);
    }
}

// ---------------- K3: parallel emit (one block per kp channel) --------------
// out layout (9472 f32): root[256][2] | kp[256][17][2] | valid[256]
__global__ void __launch_bounds__(256) k_emit(const float* __restrict__ x,
                                              float* __restrict__ out) {
    int b = blockIdx.x;
    int t = threadIdx.x;           // 256 threads = one root each
    int ns = g_nsel;
    const float Z = 1.41421356237309515f * 1024.0f;  // sqrt(2)*S

    if (b < NKP) {
        int r = t;
        float kx = 0.0f, ky = 0.0f;
        if (r < ns) {
            int xi = g_selx[r], yi = g_sely[r];
            int off = yi * S + xi;
            float dxv = x[(1 + 2 * b) * SS + off];
            float dyv = x[(2 + 2 * b) * SS + off];
            float ddx = tanhf(dxv) * Z, ddy = tanhf(dyv) * Z;
            kx = ddx + (float)xi;
            ky = ddy + (float)yi;
            float d = sqrtf(ddx * ddx + ddy * ddy);
            if (d < 2.0f) { kx = 0.0f; ky = 0.0f; }
            kx *= 4.0f; ky *= 4.0f;
        }
        int j = r * NKP + b;
        out[2 * MAXR + 2 * j]     = kx;
        out[2 * MAXR + 2 * j + 1] = ky;
    } else {
        // roots + valid + scratch cleanup for next replay
        int r = t;
        bool v = (r < ns);
        float fx = v ? (float)g_selx[r] : 0.0f;
        float fy = v ? (float)g_sely[r] : 0.0f;
        out[2 * r]     = fx * 4.0f;
        out[2 * r + 1] = fy * 4.0f;
        out[2 * MAXR + MAXR * 2 * NKP + r] = v ? 1.0f : 0.0f;
        for (int h = t; h < NBH; h += 256) g_hist[h] = 0u;
        if (t == 0) g_cnt_hot = 0u;
    }
}

// ---------------- entry ----------------
extern "C" void kernel_launch(void* const* d_in, const int* in_sizes, int n_in,
                              void* d_out, int out_size) {
    const float* x = (const float*)d_in[0];
    float* out = (float*)d_out;
    (void)in_sizes; (void)n_in; (void)out_size;

    k_scan<<<SS / 8 / 512, 512>>>(x);
    k_mid<<<1, 1024>>>();
    k_emit<<<NKP + 1, 256>>>(x, out);
}

// round 14
// speedup vs baseline: 1.1948x; 1.0260x over previous
#include <cuda_runtime.h>
#include <math.h>
#include <stdint.h>

#define S 1024
#define SS (S*S)
#define NBH 4096
#define CAP 512
#define TARGETN 384u
#define MAXR 256
#define NKP 17
#define HOTCAP 8192
#define NW2 12              // 384/32 bitset words for MIS
#define MPAD 13             // padded row stride (bank-conflict-free)
#define FULL 0xFFFFFFFFu

#define HOTB  0x3F733333u   // __float_as_uint(0.95f)
#define HRNG  (0x3F800000u - 0x3F733333u)

// ---------------- scratch (static __device__, zero at module load) ----------
__device__ unsigned int       g_hist[NBH];
__device__ unsigned int       g_cnt_hot;
__device__ unsigned long long g_hot[HOTCAP];   // hot candidates (bits<<32 | ~idx)
__device__ int                g_selx[MAXR], g_sely[MAXR];
__device__ int                g_nsel;

static __device__ __forceinline__ unsigned bucket_hot(unsigned bits) {
    unsigned d = bits - HOTB;
    unsigned b = (unsigned)(((unsigned long long)d * NBH) / HRNG);
    return b >= NBH ? (NBH - 1) : b;
}

// ---------------- K1: scan heatmap; keep only conf>=0.95 candidates ---------
__global__ void __launch_bounds__(512) k_scan(const float* __restrict__ x) {
    // let the dependent k_mid begin its launch prologue immediately
    cudaTriggerProgrammaticLaunchCompletion();

    const float4* __restrict__ x4 = (const float4*)x;
    int i = blockIdx.x * blockDim.x + threadIdx.x;   // SS/8 threads
    int lane = threadIdx.x & 31;

    float4 a0 = x4[i];
    float4 a1 = x4[i + SS / 8];
    float vs[8] = {a0.x, a0.y, a0.z, a0.w, a1.x, a1.y, a1.z, a1.w};

    unsigned long long keys[8];
    unsigned bbits[8];
    int cnt = 0;
    #pragma unroll
    for (int c = 0; c < 8; c++) {
        float v = vs[c];
        if (v > 2.9f) {  // prefilter; exact test on conf bits below
            float conf = 1.0f / (1.0f + expf(-v));   // same formula as reference
            unsigned bits = __float_as_uint(conf);
            if (bits >= HOTB) {
                int idx = (c < 4) ? (4 * i + c) : (4 * (i + SS / 8) + (c - 4));
                keys[cnt]  = ((unsigned long long)bits << 32) | (unsigned)(~idx);
                bbits[cnt] = bits;
                cnt++;
            }
        }
    }
    if (__ballot_sync(FULL, cnt) == 0u) return;   // ~99% of warps exit here

    unsigned pre = (unsigned)cnt;
    #pragma unroll
    for (int off = 1; off < 32; off <<= 1) {
        unsigned v = __shfl_up_sync(FULL, pre, off);
        if (lane >= off) pre += v;
    }
    unsigned total = __shfl_sync(FULL, pre, 31);
    unsigned base = 0;
    if (lane == 31) base = atomicAdd(&g_cnt_hot, total);
    base = __shfl_sync(FULL, base, 31);
    unsigned mybase = base + pre - (unsigned)cnt;
    for (int c = 0; c < cnt; c++) {
        unsigned p = mybase + c;
        if (p < HOTCAP) g_hot[p] = keys[c];
        atomicAdd(&g_hist[bucket_hot(bbits[c])], 1u);   // RED
    }
}

// ---------------- K2: cutoff + collect + reg-sort + build + pingpong-MIS ----
__global__ void __launch_bounds__(1024, 1) k_mid() {
    __shared__ unsigned long long sk[CAP];          // 4 KB (buffer A)
    __shared__ unsigned long long sk2[CAP];         // 4 KB (buffer B)
    __shared__ float2  pos[CAP];                    // 4 KB
    __shared__ unsigned s_mtx[384 * MPAD];          // ~19.5 KB conflict matrix
    __shared__ unsigned cs[1024];
    __shared__ unsigned seg_suf[32];
    __shared__ unsigned s_cut;
    __shared__ unsigned s_cnt;
    __shared__ unsigned s_und[2][NW2], s_acc[2][NW2];
    __shared__ unsigned s_accw[NW2];

    int t = threadIdx.x;
    int lane = t & 31;

    // wait for k_scan's writes, then let k_emit begin its launch prologue
    cudaGridDependencySynchronize();
    cudaTriggerProgrammaticLaunchCompletion();

    // --- phase A: per-4-bucket partial sums + init ---
    {
        unsigned s = 0;
        #pragma unroll
        for (int b = 0; b < 4; b++) s += g_hist[t * 4 + b];
        cs[t] = s;
        if (t == 0) s_cnt = 0u;
        if (t < CAP) sk[t] = 0ULL;
    }
    __syncthreads();

    // --- phase B: parallel cutoff; strictly above boundary bucket ---
    if (t < 32) {
        unsigned a = 0;
        #pragma unroll
        for (int b = 0; b < 32; b++) a += cs[lane * 32 + b];
        unsigned suf = a;
        #pragma unroll
        for (int off = 1; off < 32; off <<= 1) {
            unsigned v = __shfl_down_sync(FULL, suf, off);
            if (lane + off < 32) suf += v;
        }
        seg_suf[lane] = suf;
        __syncwarp(FULL);
        unsigned bal = __ballot_sync(FULL, suf >= TARGETN);
        if (lane == 0) {
            if (bal == 0u) { s_cut = 0u; }  // total hot < TARGETN: keep all (<384)
            else {
                int lseg = 31 - __clz(bal);
                unsigned base = (lseg < 31) ? seg_suf[lseg + 1] : 0u;
                unsigned cum = base;
                int ccut = lseg * 32;
                for (int c = lseg * 32 + 31; c >= lseg * 32; c--) {
                    cum += cs[c];
                    if (cum >= TARGETN) { ccut = c; break; }
                }
                unsigned cc = cum - cs[ccut];
                unsigned h[4];
                #pragma unroll
                for (int b = 0; b < 4; b++) h[b] = g_hist[ccut * 4 + b];
                int bcut = ccut * 4;
                #pragma unroll
                for (int b = 3; b >= 0; b--) {
                    cc += h[b];
                    if (cc >= TARGETN) { bcut = ccut * 4 + b; break; }
                }
                s_cut = (unsigned)bcut + 1u;  // strict-above => count < TARGETN
            }
        }
    }
    __syncthreads();

    // --- phase C: collect above cutoff (warp-aggregated smem append) --------
    {
        unsigned n = min(g_cnt_hot, (unsigned)HOTCAP);
        unsigned cut = s_cut;
        unsigned rounds = (n + 1023u) / 1024u;
        for (unsigned r = 0; r < rounds; r++) {
            unsigned i = r * 1024u + (unsigned)t;
            bool keep = false;
            unsigned long long key = 0ULL;
            if (i < n) {
                key = g_hot[i];
                keep = bucket_hot((unsigned)(key >> 32)) >= cut;
            }
            unsigned bal = __ballot_sync(FULL, keep);
            if (bal) {
                unsigned wcnt = __popc(bal);
                unsigned base = 0;
                if (lane == 0) base = atomicAdd(&s_cnt, wcnt);
                base = __shfl_sync(FULL, base, 0);
                if (keep) {
                    unsigned p = base + __popc(bal & ((1u << lane) - 1u));
                    if (p < CAP) sk[p] = key;
                }
            }
        }
    }
    __syncthreads();

    // --- phase D: register bitonic sort desc, ping-pong smem (1 bar/stage) --
    unsigned long long key = (t < CAP) ? sk[t] : 0ULL;
    {
        int pp = 0;
        for (int k = 2; k <= CAP; k <<= 1) {
            for (int j = k >> 1; j > 0; j >>= 1) {
                unsigned long long other;
                if (j >= 32) {
                    unsigned long long* wbuf = pp ? sk2 : sk;
                    if (t < CAP) wbuf[t] = key;
                    __syncthreads();
                    other = (t < CAP) ? wbuf[t ^ j] : key;
                    pp ^= 1;
                } else {
                    other = __shfl_xor_sync(FULL, key, j);
                }
                bool keepMax = (((t & j) == 0) == ((t & k) == 0));
                if (keepMax ? (other > key) : (other < key)) key = other;
            }
        }
    }
    unsigned m = min(s_cnt, (unsigned)CAP);   // m < 384 guaranteed
    if (t < CAP) {
        unsigned idx = ~(unsigned)key;
        pos[t] = make_float2((float)(idx & (S - 1)), (float)(idx >> 10));
    }
    // zero conflict matrix + init MIS state (buffer 0)
    for (int i = t; i < 384 * MPAD; i += 1024) s_mtx[i] = 0u;
    {
        unsigned alive = __ballot_sync(FULL, t < (int)m);
        if (t < NW2 * 32 && lane == 0) { s_und[0][t >> 5] = alive; s_acc[0][t >> 5] = 0u; }
    }
    __syncthreads();

    // --- phase E1: split-build triangular conflict matrix (2 thr/candidate) -
    {
        int i   = (t < 384) ? t : t - 384;
        int par = (t < 384) ? 0 : 1;
        if (t < 768 && i < (int)m) {
            float2 p = pos[i];
            int wi2 = i >> 5;
            int li = i & 31;
            for (int w = par; w <= wi2; w += 2) {
                int jmax = (w == wi2) ? li : 32;
                unsigned mw = 0u;
                for (int l = 0; l < jmax; l++) {
                    float2 q = pos[w * 32 + l];   // broadcast LDS
                    float dx = p.x - q.x, dy = p.y - q.y;
                    if (dx * dx + dy * dy <= 100.0f) mw |= 1u << l;
                }
                if (mw) s_mtx[i * MPAD + w] = mw;
            }
        }
    }
    __syncthreads();

    // --- phase E2: lexicographic MIS relaxation, warps 0-11 only ------------
    if (t < 384) {
        float2 myp = (t < (int)m) ? pos[t] : make_float2(0.f, 0.f);
        int wi = t >> 5;
        unsigned msk[NW2];
        #pragma unroll
        for (int w = 0; w < NW2; w++) msk[w] = 0u;
        if (t < (int)m) {
            #pragma unroll
            for (int w = 0; w < NW2; w++) msk[w] = s_mtx[t * MPAD + w];
        }
        bool undec = (t < (int)m);
        bool isacc = false;
        int cur = 0;

        for (int round = 0; round < 384; round++) {
            unsigned u[NW2], a[NW2], u_all = 0u;
            #pragma unroll
            for (int w = 0; w < NW2; w++) {
                u[w] = s_und[cur][w];
                a[w] = s_acc[cur][w];
                u_all |= u[w];
            }
            if (u_all == 0u) break;          // uniform (same smem for all)
            if (undec) {
                unsigned pend = 0u, accc = 0u;
                #pragma unroll
                for (int w = 0; w < NW2; w++) { pend |= msk[w] & u[w]; accc |= msk[w] & a[w]; }
                if (pend == 0u) { undec = false; isacc = (accc == 0u); }
            }
            unsigned uw = __ballot_sync(FULL, undec);
            unsigned aw = __ballot_sync(FULL, isacc);
            if (lane == 0) {
                s_und[cur ^ 1][wi] = uw;
                s_acc[cur ^ 1][wi] = aw;
            }
            asm volatile("bar.sync 1, 384;" ::: "memory");
            cur ^= 1;
        }
        // republish final accepted words at stable location
        if (t < NW2) s_accw[t] = s_acc[cur][t];
    }
    __syncthreads();

    // --- extract accepted in rank order, cap MAXR ---
    if (t < (int)m) {
        int wi = t >> 5;
        unsigned aw = s_accw[wi];
        if ((aw >> lane) & 1u) {
            int below = 0;
            #pragma unroll
            for (int w = 0; w < NW2; w++) if (w < wi) below += __popc(s_accw[w]);
            below += __popc(aw & ((1u << lane) - 1u));
            if (below < MAXR) {
                float2 p = pos[t];
                g_selx[below] = (int)p.x;
                g_sely[below] = (int)p.y;
            }
        }
    }
    if (t == 0) {
        int tot = 0;
        #pragma unroll
        for (int w = 0; w < NW2; w++) tot += __popc(s_accw[w]);
        g_nsel = min(tot, MAXR);
    }
}

// ---------------- K3: parallel emit (one block per kp channel) --------------
// out layout (9472 f32): root[256][2] | kp[256][17][2] | valid[256]
__global__ void __launch_bounds__(256) k_emit(const float* __restrict__ x,
                                              float* __restrict__ out) {
    // wait for k_mid's g_sel*/g_nsel writes
    cudaGridDependencySynchronize();

    int b = blockIdx.x;
    int t = threadIdx.x;           // 256 threads = one root each
    int ns = g_nsel;
    const float Z = 1.41421356237309515f * 1024.0f;  // sqrt(2)*S

    if (b < NKP) {
        int r = t;
        float kx = 0.0f, ky = 0.0f;
        if (r < ns) {
            int xi = g_selx[r], yi = g_sely[r];
            int off = yi * S + xi;
            float dxv = x[(1 + 2 * b) * SS + off];
            float dyv = x[(2 + 2 * b) * SS + off];
            float ddx = tanhf(dxv) * Z, ddy = tanhf(dyv) * Z;
            kx = ddx + (float)xi;
            ky = ddy + (float)yi;
            float d = sqrtf(ddx * ddx + ddy * ddy);
            if (d < 2.0f) { kx = 0.0f; ky = 0.0f; }
            kx *= 4.0f; ky *= 4.0f;
        }
        int j = r * NKP + b;
        out[2 * MAXR + 2 * j]     = kx;
        out[2 * MAXR + 2 * j + 1] = ky;
    } else {
        // roots + valid + scratch cleanup for next replay
        int r = t;
        bool v = (r < ns);
        float fx = v ? (float)g_selx[r] : 0.0f;
        float fy = v ? (float)g_sely[r] : 0.0f;
        out[2 * r]     = fx * 4.0f;
        out[2 * r + 1] = fy * 4.0f;
        out[2 * MAXR + MAXR * 2 * NKP + r] = v ? 1.0f : 0.0f;
        for (int h = t; h < NBH; h += 256) g_hist[h] = 0u;
        if (t == 0) g_cnt_hot = 0u;
    }
}

// ---------------- entry ----------------
extern "C" void kernel_launch(void* const* d_in, const int* in_sizes, int n_in,
                              void* d_out, int out_size) {
    const float* x = (const float*)d_in[0];
    float* out = (float*)d_out;
    (void)in_sizes; (void)n_in; (void)out_size;

    // K1: normal launch
    k_scan<<<SS / 8 / 512, 512>>>(x);

    // K2: PDL — launch prologue overlaps k_scan execution
    {
        cudaLaunchConfig_t cfg = {};
        cfg.gridDim = dim3(1, 1, 1);
        cfg.blockDim = dim3(1024, 1, 1);
        cfg.dynamicSmemBytes = 0;
        cfg.stream = 0;
        cudaLaunchAttribute attr[1];
        attr[0].id = cudaLaunchAttributeProgrammaticStreamSerialization;
        attr[0].val.programmaticStreamSerializationAllowed = 1;
        cfg.attrs = attr;
        cfg.numAttrs = 1;
        cudaLaunchKernelEx(&cfg, k_mid);
    }

    // K3: PDL — launch prologue overlaps k_mid execution
    {
        cudaLaunchConfig_t cfg = {};
        cfg.gridDim = dim3(NKP + 1, 1, 1);
        cfg.blockDim = dim3(256, 1, 1);
        cfg.dynamicSmemBytes = 0;
        cfg.stream = 0;
        cudaLaunchAttribute attr[1];
        attr[0].id = cudaLaunchAttributeProgrammaticStreamSerialization;
        attr[0].val.programmaticStreamSerializationAllowed = 1;
        cfg.attrs = attr;
        cfg.numAttrs = 1;
        cudaLaunchKernelEx(&cfg, k_emit, x, out);
    }
}